// round 10
// baseline (speedup 1.0000x reference)
#include <cuda_runtime.h>

// Bilinear 2x upsample NHWC f32: (8,256,256,32) -> (8,512,512,32).
// Y-pair kernel with fully sequential stores: one thread per (output col,
// float4 channel group), producing output rows (2k-1, 2k) which share input
// rows (k-1, k). Warp store wavefronts are 512B fully contiguous; each output
// row is written as a monotone sequential stream (tests DRAM write-burst
// sensitivity -- the output stream is the only remaining DRAM traffic).
// Closed-form scale-0.5 weights, identical math to the verified kernels.

#define IH 256
#define IW 256
#define OH 512
#define OW 512
#define C4 8          // 32 channels / 4 floats

__global__ __launch_bounds__(256) void bilinear2x_ypair_kernel(
    const float4* __restrict__ in, float4* __restrict__ out)
{
    // Thread -> (ox, c4): t = 0..4095 per (k, n) row; c4 fastest for contiguity
    const int t  = blockIdx.x * 256 + threadIdx.x;   // 16 blocks x 256 = 4096
    const int c4 = t & (C4 - 1);
    const int ox = t >> 3;                           // 0..511
    const int k  = blockIdx.y;                       // y-pair index, 0..256
    const int n  = blockIdx.z;

    // x source: gx = max(ox*0.5 - 0.25, 0); exact in fp32
    const float gx = fmaxf((float)ox * 0.5f - 0.25f, 0.0f);
    const int   x0 = (int)gx;
    const float f  = gx - (float)x0;                 // 0, 0.25 or 0.75
    const int   x1 = x0 + (x0 < IW - 1);
    const float g  = 1.0f - f;

    // y source rows for this pair (clamped)
    const int ya = max(k - 1, 0);
    const int yb = min(k, IH - 1);

    const float4* __restrict__ ibase = in + (long long)n * (IH * IW * C4);
    const float4 vaa = __ldg(ibase + (ya * IW + x0) * C4 + c4);
    const float4 vab = __ldg(ibase + (ya * IW + x1) * C4 + c4);
    const float4 vba = __ldg(ibase + (yb * IW + x0) * C4 + c4);
    const float4 vbb = __ldg(ibase + (yb * IW + x1) * C4 + c4);

    // x-interp for top and bottom input rows
    float4 tx, bx;
    tx.x = g * vaa.x + f * vab.x;  bx.x = g * vba.x + f * vbb.x;
    tx.y = g * vaa.y + f * vab.y;  bx.y = g * vba.y + f * vbb.y;
    tx.z = g * vaa.z + f * vab.z;  bx.z = g * vba.z + f * vbb.z;
    tx.w = g * vaa.w + f * vab.w;  bx.w = g * vba.w + f * vbb.w;

    // Output rows (clamped; k=0 and k=256 write their row twice with
    // identical values since ya==yb there -> deterministic, exact)
    const int r0 = max(2 * k - 1, 0);   // bottom weight 0.25
    const int r1 = min(2 * k, OH - 1);  // bottom weight 0.75

    float4* __restrict__ obase = out + (long long)n * (OH * OW * C4);

    float4 o;
    o.x = 0.75f * tx.x + 0.25f * bx.x;
    o.y = 0.75f * tx.y + 0.25f * bx.y;
    o.z = 0.75f * tx.z + 0.25f * bx.z;
    o.w = 0.75f * tx.w + 0.25f * bx.w;
    obase[r0 * (OW * C4) + t] = o;

    o.x = 0.25f * tx.x + 0.75f * bx.x;
    o.y = 0.25f * tx.y + 0.75f * bx.y;
    o.z = 0.25f * tx.z + 0.75f * bx.z;
    o.w = 0.25f * tx.w + 0.75f * bx.w;
    obase[r1 * (OW * C4) + t] = o;
}

extern "C" void kernel_launch(void* const* d_in, const int* in_sizes, int n_in,
                              void* d_out, int out_size)
{
    const float4* in  = (const float4*)d_in[0];
    float4*       out = (float4*)d_out;
    dim3 block(256, 1, 1);
    dim3 grid(OW * C4 / 256, IH + 1, 8);   // (16, 257, 8)
    bilinear2x_ypair_kernel<<<grid, block>>>(in, out);
}

// round 11
// speedup vs baseline: 1.0222x; 1.0222x over previous
#include <cuda_runtime.h>

// FINAL: Bilinear 2x upsample NHWC f32: (8,256,256,32) -> (8,512,512,32).
// Quad kernel: each thread produces a 2x2 output pixel quad from one 2x2
// input patch (per float4 channel group). Fixed fractions for scale 0.5:
// odd output row: h0=0.25, even row: h0=0.75; rows (2k-1, 2k) share input
// rows (k-1, k). Edges handled by index clamping (degenerate patches have
// equal loaded values, so result is exact regardless of weight).
//
// Measured: 49.2us kernel / 53.7us e2e; DRAM traffic ~= output stream only
// (268MB, input L2-resident) at 5.6TB/s -> within ~10% of the write-BW
// roofline. Verified plateau: dual-quad, stcs, and sequential-store variants
// all land at or above this time.

#define IH 256
#define IW 256
#define OH 512
#define OW 512
#define C4 8          // 32 channels / 4 floats

__global__ __launch_bounds__(256) void bilinear2x_quad_kernel(
    const float4* __restrict__ in, float4* __restrict__ out)
{
    // threadIdx.x: 8 channel-groups (c4, fastest) x 32 x-quads per block
    const int c4   = threadIdx.x & (C4 - 1);
    const int j    = blockIdx.x * 32 + (threadIdx.x >> 3);   // x-quad index, 0..256
    if (j > IW) return;                                       // 257 quads in x
    const int k    = blockIdx.y;                              // y-quad index, 0..256
    const int n    = blockIdx.z;

    // Input patch coords (clamped)
    const int ya = max(k - 1, 0);
    const int yb = min(k, IH - 1);
    const int xa = max(j - 1, 0);
    const int xb = min(j, IW - 1);

    const float4* __restrict__ ibase = in + (long long)n * (IH * IW * C4);
    const float4 vaa = __ldg(ibase + (ya * IW + xa) * C4 + c4);
    const float4 vab = __ldg(ibase + (ya * IW + xb) * C4 + c4);
    const float4 vba = __ldg(ibase + (yb * IW + xa) * C4 + c4);
    const float4 vbb = __ldg(ibase + (yb * IW + xb) * C4 + c4);

    // Separable x-interps: w0 = weight of the xb (right) column
    // column c0 = 2j-1 (odd)  -> w0 = 0.25
    // column c1 = 2j   (even) -> w0 = 0.75
    float4 tL, tR, bL, bR;
    tL.x = 0.75f * vaa.x + 0.25f * vab.x;  tR.x = 0.25f * vaa.x + 0.75f * vab.x;
    tL.y = 0.75f * vaa.y + 0.25f * vab.y;  tR.y = 0.25f * vaa.y + 0.75f * vab.y;
    tL.z = 0.75f * vaa.z + 0.25f * vab.z;  tR.z = 0.25f * vaa.z + 0.75f * vab.z;
    tL.w = 0.75f * vaa.w + 0.25f * vab.w;  tR.w = 0.25f * vaa.w + 0.75f * vab.w;
    bL.x = 0.75f * vba.x + 0.25f * vbb.x;  bR.x = 0.25f * vba.x + 0.75f * vbb.x;
    bL.y = 0.75f * vba.y + 0.25f * vbb.y;  bR.y = 0.25f * vba.y + 0.75f * vbb.y;
    bL.z = 0.75f * vba.z + 0.25f * vbb.z;  bR.z = 0.25f * vba.z + 0.75f * vbb.z;
    bL.w = 0.75f * vba.w + 0.25f * vbb.w;  bR.w = 0.25f * vba.w + 0.75f * vbb.w;

    // Output quad coords (clamped; edge duplicates write the same value)
    const int r0 = max(2 * k - 1, 0);
    const int r1 = min(2 * k, OH - 1);
    const int c0 = max(2 * j - 1, 0);
    const int c1 = min(2 * j, OW - 1);

    float4* __restrict__ obase = out + (long long)n * (OH * OW * C4);

    float4 o;
    // (r0, c0): h0 = 0.25 (weight of bottom row)
    o.x = 0.75f * tL.x + 0.25f * bL.x;
    o.y = 0.75f * tL.y + 0.25f * bL.y;
    o.z = 0.75f * tL.z + 0.25f * bL.z;
    o.w = 0.75f * tL.w + 0.25f * bL.w;
    obase[(r0 * OW + c0) * C4 + c4] = o;

    // (r0, c1)
    o.x = 0.75f * tR.x + 0.25f * bR.x;
    o.y = 0.75f * tR.y + 0.25f * bR.y;
    o.z = 0.75f * tR.z + 0.25f * bR.z;
    o.w = 0.75f * tR.w + 0.25f * bR.w;
    obase[(r0 * OW + c1) * C4 + c4] = o;

    // (r1, c0): h0 = 0.75
    o.x = 0.25f * tL.x + 0.75f * bL.x;
    o.y = 0.25f * tL.y + 0.75f * bL.y;
    o.z = 0.25f * tL.z + 0.75f * bL.z;
    o.w = 0.25f * tL.w + 0.75f * bL.w;
    obase[(r1 * OW + c0) * C4 + c4] = o;

    // (r1, c1)
    o.x = 0.25f * tR.x + 0.75f * bR.x;
    o.y = 0.25f * tR.y + 0.75f * bR.y;
    o.z = 0.25f * tR.z + 0.75f * bR.z;
    o.w = 0.25f * tR.w + 0.75f * bR.w;
    obase[(r1 * OW + c1) * C4 + c4] = o;
}

extern "C" void kernel_launch(void* const* d_in, const int* in_sizes, int n_in,
                              void* d_out, int out_size)
{
    const float4* in  = (const float4*)d_in[0];
    float4*       out = (float4*)d_out;
    // 257 quads per axis (edge quads are degenerate/clamped)
    dim3 block(256, 1, 1);                    // 8 c4 x 32 j
    dim3 grid((IW / 32) + 1, IH + 1, 8);      // (9, 257, 8)
    bilinear2x_quad_kernel<<<grid, block>>>(in, out);
}